// round 7
// baseline (speedup 1.0000x reference)
#include <cuda_runtime.h>
#include <math_constants.h>

// Problem constants (fixed by setup_inputs)
#define NN     50000      // nodes
#define NE     800000     // edges
#define FIN    256        // in channels
#define F1     256        // heads*hid = 4*64
#define H1     4
#define C1     64
#define F2     32         // out channels

// ---------------- scratch (__device__ globals; no allocation allowed) -------
__device__ float g_hW1[NN * F1];          // x @ W1            (51.2 MB)
__device__ float g_asrc1[NN * H1];
__device__ float g_adst1[NN * H1];
__device__ float g_hW2[NN * F2];          // elu(h) @ W2       (6.4 MB)
__device__ float g_asrc2[NN];
__device__ float g_adst2[NN];
__device__ int   g_deg[NN];
__device__ int   g_off[NN + 1];
__device__ int   g_cur[NN];
__device__ int   g_csr_src[NE];           // src node id per in-edge, bucketed by dst

// ---------------- helpers ---------------------------------------------------
__device__ __forceinline__ float leaky(float v) { return v > 0.f ? v : 0.2f * v; }
__device__ __forceinline__ float elu(float v)   { return v > 0.f ? v : (__expf(v) - 1.f); }

// f32x2 packed-FMA helpers (sm_100+; SASS FFMA2 — 2 FMA lanes per issue slot)
__device__ __forceinline__ unsigned long long pack2(float lo, float hi) {
    unsigned long long r;
    asm("mov.b64 %0, {%1, %2};" : "=l"(r) : "f"(lo), "f"(hi));
    return r;
}
__device__ __forceinline__ void fma2(unsigned long long& d, unsigned long long a,
                                     unsigned long long b) {
    asm("fma.rn.f32x2 %0, %1, %2, %0;" : "+l"(d) : "l"(a), "l"(b));
}
__device__ __forceinline__ void unpack2(unsigned long long v, float& lo, float& hi) {
    asm("mov.b64 {%0, %1}, %2;" : "=f"(lo), "=f"(hi) : "l"(v));
}

// ---------------- zero init (deg + layer-1 attention accumulators) ----------
__global__ void zero_k() {
    int i = blockIdx.x * blockDim.x + threadIdx.x;
    if (i < NN) g_deg[i] = 0;
    if (i < NN * H1) { g_asrc1[i] = 0.f; g_adst1[i] = 0.f; }
}

__global__ void hist_k(const int* __restrict__ ei) {
    int i = blockIdx.x * blockDim.x + threadIdx.x;
    if (i < NE) atomicAdd(&g_deg[ei[NE + i]], 1);
}

__global__ void scan_k() {  // 1 block, 1024 threads
    __shared__ int part[1024];
    const int t = threadIdx.x;
    const int CH = (NN + 1023) / 1024;   // 49
    int base = t * CH;
    int s = 0;
    for (int i = 0; i < CH; i++) { int idx = base + i; if (idx < NN) s += g_deg[idx]; }
    part[t] = s;
    __syncthreads();
    for (int off = 1; off < 1024; off <<= 1) {
        int v = (t >= off) ? part[t - off] : 0;
        __syncthreads();
        part[t] += v;
        __syncthreads();
    }
    int run = part[t] - s;               // exclusive prefix of this thread's chunk
    for (int i = 0; i < CH; i++) {
        int idx = base + i;
        if (idx < NN) { g_off[idx] = run; g_cur[idx] = run; run += g_deg[idx]; }
    }
    if (t == 1023) g_off[NN] = part[1023];
}

__global__ void fill_k(const int* __restrict__ ei) {
    int i = blockIdx.x * blockDim.x + threadIdx.x;
    if (i < NE) {
        int d = ei[NE + i];
        int p = atomicAdd(&g_cur[d], 1);
        g_csr_src[p] = ei[i];
    }
}

// ---------------- GEMM1 (+ fused layer-1 attention coefficients) ------------
// g_hW1 = x[NN,256] @ W1[256,256]. 128x128 tile, BK=16, register-prefetch
// pipeline + packed f32x2 FMA. Epilogue also computes this thread's partial
// <h, att_src>/<h, att_dst> (its 8 cols lie within one head) and atomically
// accumulates into g_asrc1/g_adst1 — replaces a separate att1 kernel.
__global__ __launch_bounds__(256, 2) void gemm1_k(const float* __restrict__ A,
                                                  const float* __restrict__ B,
                                                  const float* __restrict__ att_src,
                                                  const float* __restrict__ att_dst) {
    __shared__ float As[16][128];
    __shared__ float Bs[16][128];
    const int by = blockIdx.y, bx = blockIdx.x;
    const int tid = threadIdx.x;
    const int tr = tid >> 4, tc = tid & 15;

    unsigned long long acc2[4][8];   // [row-pair][col]; lanes = (row 2i, row 2i+1)
#pragma unroll
    for (int i = 0; i < 4; i++)
#pragma unroll
        for (int j = 0; j < 8; j++) acc2[i][j] = 0ull;

    // per-slot tile coordinates (2 load slots of 256 float4s each)
    int arr[2], acc_[2], brr[2], bcc[2], agr[2];
#pragma unroll
    for (int l = 0; l < 2; l++) {
        int idx = tid + l * 256;          // float4 index, 0..511
        arr[l] = idx >> 2;                // A tile row (0..127)
        acc_[l] = (idx & 3) << 2;         // A tile k   (0,4,8,12)
        brr[l] = idx >> 5;                // B tile k   (0..15)
        bcc[l] = (idx & 31) << 2;         // B tile col (0..124)
        agr[l] = by * 128 + arr[l];       // global A row
    }

    float4 pa[2], pb[2];
    // prefetch k0 = 0
#pragma unroll
    for (int l = 0; l < 2; l++) {
        pa[l] = (agr[l] < NN) ? *(const float4*)(A + (size_t)agr[l] * 256 + acc_[l])
                              : make_float4(0.f, 0.f, 0.f, 0.f);
        pb[l] = *(const float4*)(B + (size_t)brr[l] * 256 + bx * 128 + bcc[l]);
    }

    for (int k0 = 0; k0 < 256; k0 += 16) {
        // store prefetched tile to SMEM (A transposed: As[k][row])
#pragma unroll
        for (int l = 0; l < 2; l++) {
            As[acc_[l] + 0][arr[l]] = pa[l].x;
            As[acc_[l] + 1][arr[l]] = pa[l].y;
            As[acc_[l] + 2][arr[l]] = pa[l].z;
            As[acc_[l] + 3][arr[l]] = pa[l].w;
            *(float4*)&Bs[brr[l]][bcc[l]] = pb[l];
        }
        __syncthreads();

        // issue next tile's loads before computing (latency overlap)
        if (k0 < 240) {
            int kn = k0 + 16;
#pragma unroll
            for (int l = 0; l < 2; l++) {
                pa[l] = (agr[l] < NN) ? *(const float4*)(A + (size_t)agr[l] * 256 + kn + acc_[l])
                                      : make_float4(0.f, 0.f, 0.f, 0.f);
                pb[l] = *(const float4*)(B + (size_t)(kn + brr[l]) * 256 + bx * 128 + bcc[l]);
            }
        }

#pragma unroll
        for (int k = 0; k < 16; k++) {
            // A row-pairs: reinterpret LDS.128 results as 2 packed f32x2 each
            ulonglong2 au0 = *(const ulonglong2*)&As[k][tr * 8];
            ulonglong2 au1 = *(const ulonglong2*)&As[k][tr * 8 + 4];
            unsigned long long a2[4] = {au0.x, au0.y, au1.x, au1.y};
            // B cols: broadcast-pack
            float4 bv0 = *(const float4*)&Bs[k][tc * 8];
            float4 bv1 = *(const float4*)&Bs[k][tc * 8 + 4];
            unsigned long long bb[8];
            bb[0] = pack2(bv0.x, bv0.x); bb[1] = pack2(bv0.y, bv0.y);
            bb[2] = pack2(bv0.z, bv0.z); bb[3] = pack2(bv0.w, bv0.w);
            bb[4] = pack2(bv1.x, bv1.x); bb[5] = pack2(bv1.y, bv1.y);
            bb[6] = pack2(bv1.z, bv1.z); bb[7] = pack2(bv1.w, bv1.w);
#pragma unroll
            for (int i = 0; i < 4; i++)
#pragma unroll
                for (int j = 0; j < 8; j++) fma2(acc2[i][j], a2[i], bb[j]);
        }
        __syncthreads();
    }

    // fused attention-coefficient slices for this thread's 8 columns
    const int colg = bx * 128 + tc * 8;       // global column start
    const int head = colg >> 6;                // 0..3
    const int coff = colg & 63;                // offset within head
    float4 av0 = *(const float4*)(att_src + head * 64 + coff);
    float4 av1 = *(const float4*)(att_src + head * 64 + coff + 4);
    float4 dv0 = *(const float4*)(att_dst + head * 64 + coff);
    float4 dv1 = *(const float4*)(att_dst + head * 64 + coff + 4);

    // epilogue: unpack row-pairs, store hW1, accumulate attention partials
#pragma unroll
    for (int i2 = 0; i2 < 4; i2++) {
        float lo[8], hi[8];
#pragma unroll
        for (int j = 0; j < 8; j++) unpack2(acc2[i2][j], lo[j], hi[j]);
        int r0 = by * 128 + tr * 8 + 2 * i2;
        if (r0 < NN) {
            *(float4*)(g_hW1 + (size_t)r0 * 256 + colg)     = make_float4(lo[0], lo[1], lo[2], lo[3]);
            *(float4*)(g_hW1 + (size_t)r0 * 256 + colg + 4) = make_float4(lo[4], lo[5], lo[6], lo[7]);
            float ss = lo[0]*av0.x + lo[1]*av0.y + lo[2]*av0.z + lo[3]*av0.w
                     + lo[4]*av1.x + lo[5]*av1.y + lo[6]*av1.z + lo[7]*av1.w;
            float dd = lo[0]*dv0.x + lo[1]*dv0.y + lo[2]*dv0.z + lo[3]*dv0.w
                     + lo[4]*dv1.x + lo[5]*dv1.y + lo[6]*dv1.z + lo[7]*dv1.w;
            atomicAdd(&g_asrc1[r0 * 4 + head], ss);
            atomicAdd(&g_adst1[r0 * 4 + head], dd);
        }
        if (r0 + 1 < NN) {
            *(float4*)(g_hW1 + (size_t)(r0 + 1) * 256 + colg)     = make_float4(hi[0], hi[1], hi[2], hi[3]);
            *(float4*)(g_hW1 + (size_t)(r0 + 1) * 256 + colg + 4) = make_float4(hi[4], hi[5], hi[6], hi[7]);
            float ss = hi[0]*av0.x + hi[1]*av0.y + hi[2]*av0.z + hi[3]*av0.w
                     + hi[4]*av1.x + hi[5]*av1.y + hi[6]*av1.z + hi[7]*av1.w;
            float dd = hi[0]*dv0.x + hi[1]*dv0.y + hi[2]*dv0.z + hi[3]*dv0.w
                     + hi[4]*dv1.x + hi[5]*dv1.y + hi[6]*dv1.z + hi[7]*dv1.w;
            atomicAdd(&g_asrc1[(r0 + 1) * 4 + head], ss);
            atomicAdd(&g_adst1[(r0 + 1) * 4 + head], dd);
        }
    }
}

// ---------------- layer-1 online softmax + aggregate + bias + ELU -----------
// One warp per destination node. Lane owns channels lane*8..lane*8+7
// (head = lane>>3). Single pass: running max with (denom, acc) rescaling.
// Depth-2 software pipeline: loads for edge i+2 issued before computing edge i.
__global__ __launch_bounds__(256) void agg1_k(const float* __restrict__ b1,
                                              float* __restrict__ hout) {
    int node = (blockIdx.x * blockDim.x + threadIdx.x) >> 5;
    int lane = threadIdx.x & 31;
    if (node >= NN) return;

    int start = g_off[node], end = g_off[node + 1];
    int cnt = end - start;

    int head = lane >> 3;
    float adst = g_adst1[node * 4 + head];

    float m = -CUDART_INF_F;
    float denom = 0.f;
    float acc[8];
#pragma unroll
    for (int q = 0; q < 8; q++) acc[q] = 0.f;

    if (cnt > 0) {
        float  asP[2];
        float4 aP[2], bP[2];
        {
            int j0 = g_csr_src[start];
            asP[0] = g_asrc1[j0 * 4 + head];
            const float4* h0 = (const float4*)(g_hW1 + (size_t)j0 * 256 + lane * 8);
            aP[0] = h0[0]; bP[0] = h0[1];
        }
        if (cnt > 1) {
            int j1 = g_csr_src[start + 1];
            asP[1] = g_asrc1[j1 * 4 + head];
            const float4* h1 = (const float4*)(g_hW1 + (size_t)j1 * 256 + lane * 8);
            aP[1] = h1[0]; bP[1] = h1[1];
        }
        for (int i = 0; i < cnt; i++) {
            int slot = i & 1;
            float as_c = asP[slot]; float4 a_c = aP[slot], b_c = bP[slot];
            if (i + 2 < cnt) {
                int jn = g_csr_src[start + i + 2];
                asP[slot] = g_asrc1[jn * 4 + head];
                const float4* hn = (const float4*)(g_hW1 + (size_t)jn * 256 + lane * 8);
                aP[slot] = hn[0]; bP[slot] = hn[1];
            }
            float v = leaky(as_c + adst);
            if (v > m) {                 // online rescale (expf(-inf)=0 seeds cleanly)
                float sc = __expf(m - v);
                denom *= sc;
#pragma unroll
                for (int q = 0; q < 8; q++) acc[q] *= sc;
                m = v;
            }
            float ex = __expf(v - m);
            denom += ex;
            acc[0] += ex * a_c.x; acc[1] += ex * a_c.y; acc[2] += ex * a_c.z; acc[3] += ex * a_c.w;
            acc[4] += ex * b_c.x; acc[5] += ex * b_c.y; acc[6] += ex * b_c.z; acc[7] += ex * b_c.w;
        }
    }
    float inv = 1.f / (denom + 1e-16f);
    int c0 = lane * 8;
    const float4* bp = (const float4*)(b1 + c0);
    float4 bb0 = bp[0], bb1 = bp[1];
    float4 o0, o1;
    o0.x = elu(acc[0] * inv + bb0.x); o0.y = elu(acc[1] * inv + bb0.y);
    o0.z = elu(acc[2] * inv + bb0.z); o0.w = elu(acc[3] * inv + bb0.w);
    o1.x = elu(acc[4] * inv + bb1.x); o1.y = elu(acc[5] * inv + bb1.y);
    o1.z = elu(acc[6] * inv + bb1.z); o1.w = elu(acc[7] * inv + bb1.w);
    float4* op = (float4*)(hout + (size_t)node * 256 + c0);
    op[0] = o0; op[1] = o1;
}

// ---------------- GEMM2 + layer-2 attention coefficients --------------------
// g_hW2 = elu_h[NN,256] @ W2[256,32]; fused a_src2/a_dst2 via warp reduction.
__global__ __launch_bounds__(256) void gemm2_k(const float* __restrict__ h,
                                               const float* __restrict__ W2,
                                               const float* __restrict__ att_src2,
                                               const float* __restrict__ att_dst2) {
    __shared__ float sW[256 * 32];
    int tid = threadIdx.x;
    for (int i = tid; i < 256 * 32; i += 256) sW[i] = W2[i];
    __syncthreads();
    int lane = tid & 31, wid = tid >> 5;
    int n = blockIdx.x * 8 + wid;
    if (n >= NN) return;

    const float4* hp = (const float4*)(h + (size_t)n * 256);
    float acc = 0.f;
#pragma unroll
    for (int k4 = 0; k4 < 64; k4++) {
        float4 hv = hp[k4];
        acc += hv.x * sW[(k4 * 4 + 0) * 32 + lane];
        acc += hv.y * sW[(k4 * 4 + 1) * 32 + lane];
        acc += hv.z * sW[(k4 * 4 + 2) * 32 + lane];
        acc += hv.w * sW[(k4 * 4 + 3) * 32 + lane];
    }
    g_hW2[n * 32 + lane] = acc;
    float s = acc * att_src2[lane];
    float d = acc * att_dst2[lane];
#pragma unroll
    for (int o = 16; o; o >>= 1) {
        s += __shfl_xor_sync(0xffffffffu, s, o);
        d += __shfl_xor_sync(0xffffffffu, d, o);
    }
    if (lane == 0) { g_asrc2[n] = s; g_adst2[n] = d; }
}

// ---------------- layer-2 online softmax + aggregate + bias -----------------
// Depth-2 software pipeline like agg1.
__global__ __launch_bounds__(256) void agg2_k(const float* __restrict__ b2,
                                              float* __restrict__ out2) {
    int node = (blockIdx.x * blockDim.x + threadIdx.x) >> 5;
    int lane = threadIdx.x & 31;
    if (node >= NN) return;

    int start = g_off[node], end = g_off[node + 1];
    int cnt = end - start;
    float adst = g_adst2[node];

    float m = -CUDART_INF_F;
    float denom = 0.f, acc = 0.f;
    if (cnt > 0) {
        float asP[2], hvP[2];
        {
            int j0 = g_csr_src[start];
            asP[0] = g_asrc2[j0];
            hvP[0] = g_hW2[j0 * 32 + lane];
        }
        if (cnt > 1) {
            int j1 = g_csr_src[start + 1];
            asP[1] = g_asrc2[j1];
            hvP[1] = g_hW2[j1 * 32 + lane];
        }
        for (int i = 0; i < cnt; i++) {
            int slot = i & 1;
            float as_c = asP[slot], hv_c = hvP[slot];
            if (i + 2 < cnt) {
                int jn = g_csr_src[start + i + 2];
                asP[slot] = g_asrc2[jn];
                hvP[slot] = g_hW2[jn * 32 + lane];
            }
            float v = leaky(as_c + adst);
            if (v > m) {                 // online rescale
                float sc = __expf(m - v);
                denom *= sc;
                acc *= sc;
                m = v;
            }
            float ex = __expf(v - m);
            denom += ex;
            acc += ex * hv_c;
        }
    }
    out2[(size_t)node * 32 + lane] = acc / (denom + 1e-16f) + b2[lane];
}

// ---------------- launch ----------------------------------------------------
extern "C" void kernel_launch(void* const* d_in, const int* in_sizes, int n_in,
                              void* d_out, int out_size) {
    const float* x   = (const float*)d_in[0];
    const float* W1  = (const float*)d_in[1];
    const float* as1 = (const float*)d_in[2];
    const float* ad1 = (const float*)d_in[3];
    const float* b1  = (const float*)d_in[4];
    const float* W2  = (const float*)d_in[5];
    const float* as2 = (const float*)d_in[6];
    const float* ad2 = (const float*)d_in[7];
    const float* b2  = (const float*)d_in[8];
    const int*   ei  = (const int*)d_in[9];

    float* out2 = (float*)d_out;                  // [NN, 32]
    float* hout = (float*)d_out + (size_t)NN * 32; // [NN, 256] (= elu layer-1 out)

    const int warpBlocks = (NN * 32 + 255) / 256;  // warp-per-node kernels
    const int edgeBlocks = (NE + 255) / 256;
    const int zeroBlocks = (NN * H1 + 255) / 256;

    // zero (deg + att1 accumulators), then CSR build (independent of GEMM1)
    zero_k<<<zeroBlocks, 256>>>();
    hist_k<<<edgeBlocks, 256>>>(ei);
    scan_k<<<1, 1024>>>();
    fill_k<<<edgeBlocks, 256>>>(ei);

    // Layer 1 (gemm1 fuses the att1 coefficient computation)
    gemm1_k<<<dim3(2, (NN + 127) / 128), 256>>>(x, W1, as1, ad1);
    agg1_k<<<warpBlocks, 256>>>(b1, hout);

    // Layer 2
    gemm2_k<<<(NN + 7) / 8, 256>>>(hout, W2, as2, ad2);
    agg2_k<<<warpBlocks, 256>>>(b2, out2);
}

// round 11
// speedup vs baseline: 1.2664x; 1.2664x over previous
#include <cuda_runtime.h>
#include <math_constants.h>
#include <cstdint>

// Problem constants (fixed by setup_inputs)
#define NN     50000      // nodes
#define NE     800000     // edges
#define FIN    256        // in channels
#define F1     256        // heads*hid = 4*64
#define H1     4
#define C1     64
#define F2     32         // out channels

// ---------------- scratch (__device__ globals; no allocation allowed) -------
__device__ float g_hW1[NN * F1];          // x @ W1            (51.2 MB)
__device__ float g_asrc1[NN * H1];
__device__ float g_adst1[NN * H1];
__device__ float g_hW2[NN * F2];          // elu(h) @ W2       (6.4 MB)
__device__ float g_asrc2[NN];
__device__ float g_adst2[NN];
__device__ int   g_deg[NN];
__device__ int   g_off[NN + 1];
__device__ int   g_cur[NN];
__device__ int   g_csr_src[NE];           // src node id per in-edge, bucketed by dst

// ---------------- helpers ---------------------------------------------------
__device__ __forceinline__ float leaky(float v) { return v > 0.f ? v : 0.2f * v; }
__device__ __forceinline__ float elu(float v)   { return v > 0.f ? v : (__expf(v) - 1.f); }

__device__ __forceinline__ uint32_t f2tf(float f) {
    uint32_t r; asm("cvt.rna.tf32.f32 %0, %1;" : "=r"(r) : "f"(f)); return r;
}
__device__ __forceinline__ void mma_tf32(float& d0, float& d1, float& d2, float& d3,
                                         uint32_t a0, uint32_t a1, uint32_t a2, uint32_t a3,
                                         uint32_t b0, uint32_t b1) {
    asm("mma.sync.aligned.m16n8k8.row.col.f32.tf32.tf32.f32 "
        "{%0,%1,%2,%3}, {%4,%5,%6,%7}, {%8,%9}, {%0,%1,%2,%3};"
        : "+f"(d0), "+f"(d1), "+f"(d2), "+f"(d3)
        : "r"(a0), "r"(a1), "r"(a2), "r"(a3), "r"(b0), "r"(b1));
}

// ---------------- zero init (deg + layer-1 attention accumulators) ----------
__global__ void zero_k() {
    int i = blockIdx.x * blockDim.x + threadIdx.x;
    if (i < NN) g_deg[i] = 0;
    if (i < NN * H1) { g_asrc1[i] = 0.f; g_adst1[i] = 0.f; }
}

// 4 independent edges per thread -> MLP 4 on the gmem atomics (latency-bound)
#define EPT 4
__global__ void hist_k(const int* __restrict__ ei) {
    int base = blockIdx.x * (256 * EPT) + threadIdx.x;
#pragma unroll
    for (int k = 0; k < EPT; k++) {
        int i = base + k * 256;
        if (i < NE) atomicAdd(&g_deg[ei[NE + i]], 1);
    }
}

__global__ void scan_k() {  // 1 block, 1024 threads
    __shared__ int part[1024];
    const int t = threadIdx.x;
    const int CH = (NN + 1023) / 1024;   // 49
    int base = t * CH;
    int s = 0;
    for (int i = 0; i < CH; i++) { int idx = base + i; if (idx < NN) s += g_deg[idx]; }
    part[t] = s;
    __syncthreads();
    for (int off = 1; off < 1024; off <<= 1) {
        int v = (t >= off) ? part[t - off] : 0;
        __syncthreads();
        part[t] += v;
        __syncthreads();
    }
    int run = part[t] - s;               // exclusive prefix of this thread's chunk
    for (int i = 0; i < CH; i++) {
        int idx = base + i;
        if (idx < NN) { g_off[idx] = run; g_cur[idx] = run; run += g_deg[idx]; }
    }
    if (t == 1023) g_off[NN] = part[1023];
}

__global__ void fill_k(const int* __restrict__ ei) {
    int base = blockIdx.x * (256 * EPT) + threadIdx.x;
#pragma unroll
    for (int k = 0; k < EPT; k++) {
        int i = base + k * 256;
        if (i < NE) {
            int d = ei[NE + i];
            int p = atomicAdd(&g_cur[d], 1);
            g_csr_src[p] = ei[i];
        }
    }
}

// ---------------- GEMM1 (tf32 tensor cores + fused att1 coefficients) -------
// g_hW1 = x[NN,256] @ W1[256,256]. 128x128 block tile, BK=16, register-prefetch
// staging (fp32 -> tf32 at SMEM store), mma.sync.m16n8k8 tf32 math.
// 8 warps: warp (wr = w&3) rows 32, (wc = w>>2) cols 64 -> 2 m-tiles x 8 n-tiles.
// Epilogue stores hW1 and atomically accumulates <h,att_src>/<h,att_dst>
// partials into g_asrc1/g_adst1 (4 partials per (row,head)).
#define AS_LD 20    // A smem row stride (conflict-free for frag loads)
#define BS_LD 136   // B smem row stride
__global__ __launch_bounds__(256, 2) void gemm1_k(const float* __restrict__ A,
                                                  const float* __restrict__ B,
                                                  const float* __restrict__ att_src,
                                                  const float* __restrict__ att_dst) {
    __shared__ __align__(16) uint32_t As[128 * AS_LD];  // [row][k] tf32
    __shared__ __align__(16) uint32_t Bs[16 * BS_LD];   // [k][n]  tf32
    const int by = blockIdx.y, bx = blockIdx.x;
    const int tid = threadIdx.x;
    const int lane = tid & 31, w = tid >> 5;
    const int wr = w & 3, wc = w >> 2;
    const int g = lane >> 2, c = lane & 3;

    float d[2][8][4];                          // [m-tile][n-tile][frag]
#pragma unroll
    for (int mi = 0; mi < 2; mi++)
#pragma unroll
        for (int ni = 0; ni < 8; ni++)
#pragma unroll
            for (int q = 0; q < 4; q++) d[mi][ni][q] = 0.f;

    // staging coordinates (2 slots of 256 float4 each)
    int arr[2], ack[2], brr[2], bcc[2], agr[2];
#pragma unroll
    for (int l = 0; l < 2; l++) {
        int idx = tid + l * 256;
        arr[l] = idx >> 2;                 // A row 0..127
        ack[l] = (idx & 3) << 2;           // A k offset 0,4,8,12
        brr[l] = idx >> 5;                 // B k 0..15
        bcc[l] = (idx & 31) << 2;          // B col 0..124
        agr[l] = by * 128 + arr[l];
    }

    float4 pa[2], pb[2];
#pragma unroll
    for (int l = 0; l < 2; l++) {
        pa[l] = (agr[l] < NN) ? *(const float4*)(A + (size_t)agr[l] * 256 + ack[l])
                              : make_float4(0.f, 0.f, 0.f, 0.f);
        pb[l] = *(const float4*)(B + (size_t)brr[l] * 256 + bx * 128 + bcc[l]);
    }

    for (int k0 = 0; k0 < 256; k0 += 16) {
        // convert to tf32 and store staged tiles
#pragma unroll
        for (int l = 0; l < 2; l++) {
            uint4 av; av.x = f2tf(pa[l].x); av.y = f2tf(pa[l].y);
                     av.z = f2tf(pa[l].z); av.w = f2tf(pa[l].w);
            *(uint4*)&As[arr[l] * AS_LD + ack[l]] = av;
            uint4 bv; bv.x = f2tf(pb[l].x); bv.y = f2tf(pb[l].y);
                     bv.z = f2tf(pb[l].z); bv.w = f2tf(pb[l].w);
            *(uint4*)&Bs[brr[l] * BS_LD + bcc[l]] = bv;
        }
        __syncthreads();

        if (k0 < 240) {
            int kn = k0 + 16;
#pragma unroll
            for (int l = 0; l < 2; l++) {
                pa[l] = (agr[l] < NN) ? *(const float4*)(A + (size_t)agr[l] * 256 + kn + ack[l])
                                      : make_float4(0.f, 0.f, 0.f, 0.f);
                pb[l] = *(const float4*)(B + (size_t)(kn + brr[l]) * 256 + bx * 128 + bcc[l]);
            }
        }

#pragma unroll
        for (int ks = 0; ks < 2; ks++) {
            const int kb = ks * 8;
            uint32_t a[2][4];
#pragma unroll
            for (int mi = 0; mi < 2; mi++) {
                int rowb = wr * 32 + mi * 16 + g;
                a[mi][0] = As[(rowb)     * AS_LD + kb + c];
                a[mi][1] = As[(rowb + 8) * AS_LD + kb + c];
                a[mi][2] = As[(rowb)     * AS_LD + kb + c + 4];
                a[mi][3] = As[(rowb + 8) * AS_LD + kb + c + 4];
            }
            uint32_t bf[8][2];
#pragma unroll
            for (int ni = 0; ni < 8; ni++) {
                int colb = wc * 64 + ni * 8 + g;
                bf[ni][0] = Bs[(kb + c)     * BS_LD + colb];
                bf[ni][1] = Bs[(kb + c + 4) * BS_LD + colb];
            }
#pragma unroll
            for (int mi = 0; mi < 2; mi++)
#pragma unroll
                for (int ni = 0; ni < 8; ni++)
                    mma_tf32(d[mi][ni][0], d[mi][ni][1], d[mi][ni][2], d[mi][ni][3],
                             a[mi][0], a[mi][1], a[mi][2], a[mi][3],
                             bf[ni][0], bf[ni][1]);
        }
        __syncthreads();
    }

    // ---- epilogue: store hW1 + fused attention partials ----
    const int head = bx * 2 + wc;              // this warp's 64-col chunk = one head
    float asv[16], adv[16];
#pragma unroll
    for (int ni = 0; ni < 8; ni++) {
        float2 s = *(const float2*)(att_src + head * 64 + ni * 8 + 2 * c);
        float2 t = *(const float2*)(att_dst + head * 64 + ni * 8 + 2 * c);
        asv[2 * ni] = s.x; asv[2 * ni + 1] = s.y;
        adv[2 * ni] = t.x; adv[2 * ni + 1] = t.y;
    }
    const int colbase = bx * 128 + wc * 64;
#pragma unroll
    for (int mi = 0; mi < 2; mi++) {
#pragma unroll
        for (int half = 0; half < 2; half++) {
            int R = by * 128 + wr * 32 + mi * 16 + half * 8 + g;
            if (R < NN) {
                float ss = 0.f, dd = 0.f;
#pragma unroll
                for (int ni = 0; ni < 8; ni++) {
                    float v0 = d[mi][ni][half * 2 + 0];
                    float v1 = d[mi][ni][half * 2 + 1];
                    *(float2*)(g_hW1 + (size_t)R * 256 + colbase + ni * 8 + 2 * c) =
                        make_float2(v0, v1);
                    ss += v0 * asv[2 * ni] + v1 * asv[2 * ni + 1];
                    dd += v0 * adv[2 * ni] + v1 * adv[2 * ni + 1];
                }
                atomicAdd(&g_asrc1[R * 4 + head], ss);
                atomicAdd(&g_adst1[R * 4 + head], dd);
            }
        }
    }
}

// ---------------- layer-1 online softmax + aggregate + bias + ELU -----------
// One warp per destination node. Lane owns channels lane*8..lane*8+7
// (head = lane>>3). Single pass: running max with (denom, acc) rescaling.
// Depth-2 software pipeline: loads for edge i+2 issued before computing edge i.
__global__ __launch_bounds__(256) void agg1_k(const float* __restrict__ b1,
                                              float* __restrict__ hout) {
    int node = (blockIdx.x * blockDim.x + threadIdx.x) >> 5;
    int lane = threadIdx.x & 31;
    if (node >= NN) return;

    int start = g_off[node], end = g_off[node + 1];
    int cnt = end - start;

    int head = lane >> 3;
    float adst = g_adst1[node * 4 + head];

    float m = -CUDART_INF_F;
    float denom = 0.f;
    float acc[8];
#pragma unroll
    for (int q = 0; q < 8; q++) acc[q] = 0.f;

    if (cnt > 0) {
        float  asP[2];
        float4 aP[2], bP[2];
        {
            int j0 = g_csr_src[start];
            asP[0] = g_asrc1[j0 * 4 + head];
            const float4* h0 = (const float4*)(g_hW1 + (size_t)j0 * 256 + lane * 8);
            aP[0] = h0[0]; bP[0] = h0[1];
        }
        if (cnt > 1) {
            int j1 = g_csr_src[start + 1];
            asP[1] = g_asrc1[j1 * 4 + head];
            const float4* h1 = (const float4*)(g_hW1 + (size_t)j1 * 256 + lane * 8);
            aP[1] = h1[0]; bP[1] = h1[1];
        }
        for (int i = 0; i < cnt; i++) {
            int slot = i & 1;
            float as_c = asP[slot]; float4 a_c = aP[slot], b_c = bP[slot];
            if (i + 2 < cnt) {
                int jn = g_csr_src[start + i + 2];
                asP[slot] = g_asrc1[jn * 4 + head];
                const float4* hn = (const float4*)(g_hW1 + (size_t)jn * 256 + lane * 8);
                aP[slot] = hn[0]; bP[slot] = hn[1];
            }
            float v = leaky(as_c + adst);
            if (v > m) {                 // online rescale (expf(-inf)=0 seeds cleanly)
                float sc = __expf(m - v);
                denom *= sc;
#pragma unroll
                for (int q = 0; q < 8; q++) acc[q] *= sc;
                m = v;
            }
            float ex = __expf(v - m);
            denom += ex;
            acc[0] += ex * a_c.x; acc[1] += ex * a_c.y; acc[2] += ex * a_c.z; acc[3] += ex * a_c.w;
            acc[4] += ex * b_c.x; acc[5] += ex * b_c.y; acc[6] += ex * b_c.z; acc[7] += ex * b_c.w;
        }
    }
    float inv = 1.f / (denom + 1e-16f);
    int c0 = lane * 8;
    const float4* bp = (const float4*)(b1 + c0);
    float4 bb0 = bp[0], bb1 = bp[1];
    float4 o0, o1;
    o0.x = elu(acc[0] * inv + bb0.x); o0.y = elu(acc[1] * inv + bb0.y);
    o0.z = elu(acc[2] * inv + bb0.z); o0.w = elu(acc[3] * inv + bb0.w);
    o1.x = elu(acc[4] * inv + bb1.x); o1.y = elu(acc[5] * inv + bb1.y);
    o1.z = elu(acc[6] * inv + bb1.z); o1.w = elu(acc[7] * inv + bb1.w);
    float4* op = (float4*)(hout + (size_t)node * 256 + c0);
    op[0] = o0; op[1] = o1;
}

// ---------------- GEMM2 + layer-2 attention coefficients --------------------
// g_hW2 = elu_h[NN,256] @ W2[256,32]; fused a_src2/a_dst2 via warp reduction.
__global__ __launch_bounds__(256) void gemm2_k(const float* __restrict__ h,
                                               const float* __restrict__ W2,
                                               const float* __restrict__ att_src2,
                                               const float* __restrict__ att_dst2) {
    __shared__ float sW[256 * 32];
    int tid = threadIdx.x;
    for (int i = tid; i < 256 * 32; i += 256) sW[i] = W2[i];
    __syncthreads();
    int lane = tid & 31, wid = tid >> 5;
    int n = blockIdx.x * 8 + wid;
    if (n >= NN) return;

    const float4* hp = (const float4*)(h + (size_t)n * 256);
    float acc = 0.f;
#pragma unroll
    for (int k4 = 0; k4 < 64; k4++) {
        float4 hv = hp[k4];
        acc += hv.x * sW[(k4 * 4 + 0) * 32 + lane];
        acc += hv.y * sW[(k4 * 4 + 1) * 32 + lane];
        acc += hv.z * sW[(k4 * 4 + 2) * 32 + lane];
        acc += hv.w * sW[(k4 * 4 + 3) * 32 + lane];
    }
    g_hW2[n * 32 + lane] = acc;
    float s = acc * att_src2[lane];
    float d = acc * att_dst2[lane];
#pragma unroll
    for (int o = 16; o; o >>= 1) {
        s += __shfl_xor_sync(0xffffffffu, s, o);
        d += __shfl_xor_sync(0xffffffffu, d, o);
    }
    if (lane == 0) { g_asrc2[n] = s; g_adst2[n] = d; }
}

// ---------------- layer-2 online softmax + aggregate + bias -----------------
// Depth-2 software pipeline like agg1.
__global__ __launch_bounds__(256) void agg2_k(const float* __restrict__ b2,
                                              float* __restrict__ out2) {
    int node = (blockIdx.x * blockDim.x + threadIdx.x) >> 5;
    int lane = threadIdx.x & 31;
    if (node >= NN) return;

    int start = g_off[node], end = g_off[node + 1];
    int cnt = end - start;
    float adst = g_adst2[node];

    float m = -CUDART_INF_F;
    float denom = 0.f, acc = 0.f;
    if (cnt > 0) {
        float asP[2], hvP[2];
        {
            int j0 = g_csr_src[start];
            asP[0] = g_asrc2[j0];
            hvP[0] = g_hW2[j0 * 32 + lane];
        }
        if (cnt > 1) {
            int j1 = g_csr_src[start + 1];
            asP[1] = g_asrc2[j1];
            hvP[1] = g_hW2[j1 * 32 + lane];
        }
        for (int i = 0; i < cnt; i++) {
            int slot = i & 1;
            float as_c = asP[slot], hv_c = hvP[slot];
            if (i + 2 < cnt) {
                int jn = g_csr_src[start + i + 2];
                asP[slot] = g_asrc2[jn];
                hvP[slot] = g_hW2[jn * 32 + lane];
            }
            float v = leaky(as_c + adst);
            if (v > m) {                 // online rescale
                float sc = __expf(m - v);
                denom *= sc;
                acc *= sc;
                m = v;
            }
            float ex = __expf(v - m);
            denom += ex;
            acc += ex * hv_c;
        }
    }
    out2[(size_t)node * 32 + lane] = acc / (denom + 1e-16f) + b2[lane];
}

// ---------------- launch ----------------------------------------------------
extern "C" void kernel_launch(void* const* d_in, const int* in_sizes, int n_in,
                              void* d_out, int out_size) {
    const float* x   = (const float*)d_in[0];
    const float* W1  = (const float*)d_in[1];
    const float* as1 = (const float*)d_in[2];
    const float* ad1 = (const float*)d_in[3];
    const float* b1  = (const float*)d_in[4];
    const float* W2  = (const float*)d_in[5];
    const float* as2 = (const float*)d_in[6];
    const float* ad2 = (const float*)d_in[7];
    const float* b2  = (const float*)d_in[8];
    const int*   ei  = (const int*)d_in[9];

    float* out2 = (float*)d_out;                  // [NN, 32]
    float* hout = (float*)d_out + (size_t)NN * 32; // [NN, 256] (= elu layer-1 out)

    const int warpBlocks = (NN * 32 + 255) / 256;      // warp-per-node kernels
    const int edgeBlocks4 = (NE + 256 * EPT - 1) / (256 * EPT);
    const int zeroBlocks = (NN * H1 + 255) / 256;

    // zero (deg + att1 accumulators), then CSR build (independent of GEMM1)
    zero_k<<<zeroBlocks, 256>>>();
    hist_k<<<edgeBlocks4, 256>>>(ei);
    scan_k<<<1, 1024>>>();
    fill_k<<<edgeBlocks4, 256>>>(ei);

    // Layer 1 (tf32 tensor-core gemm1 fuses the att1 coefficient computation)
    gemm1_k<<<dim3(2, (NN + 127) / 128), 256>>>(x, W1, as1, ad1);
    agg1_k<<<warpBlocks, 256>>>(b1, hout);

    // Layer 2
    gemm2_k<<<(NN + 7) / 8, 256>>>(hout, W2, as2, ad2);
    agg2_k<<<warpBlocks, 256>>>(b2, out2);
}

// round 14
// speedup vs baseline: 1.4733x; 1.1633x over previous
#include <cuda_runtime.h>
#include <cuda_fp16.h>
#include <math_constants.h>
#include <cstdint>

// Problem constants (fixed by setup_inputs)
#define NN     50000      // nodes
#define NE     800000     // edges
#define FIN    256        // in channels
#define F1     256        // heads*hid = 4*64
#define H1     4
#define C1     64
#define F2     32         // out channels

// ---------------- scratch (__device__ globals; no allocation allowed) -------
__device__ __half g_hW1h[NN * F1];        // x @ W1 in fp16 (25.6 MB, L2-resident)
__device__ float g_asrc1[NN * H1];
__device__ float g_adst1[NN * H1];
__device__ float g_hW2[NN * F2];          // elu(h) @ W2       (6.4 MB)
__device__ float g_asrc2[NN];
__device__ float g_adst2[NN];
__device__ int   g_deg[NN];
__device__ int   g_off[NN + 1];
__device__ int   g_cur[NN];
__device__ int   g_csr_src[NE];           // src node id per in-edge, bucketed by dst

// ---------------- helpers ---------------------------------------------------
__device__ __forceinline__ float leaky(float v) { return v > 0.f ? v : 0.2f * v; }
__device__ __forceinline__ float elu(float v)   { return v > 0.f ? v : (__expf(v) - 1.f); }

__device__ __forceinline__ uint32_t f2tf(float f) {
    uint32_t r; asm("cvt.rna.tf32.f32 %0, %1;" : "=r"(r) : "f"(f)); return r;
}
__device__ __forceinline__ void mma_tf32(float& d0, float& d1, float& d2, float& d3,
                                         uint32_t a0, uint32_t a1, uint32_t a2, uint32_t a3,
                                         uint32_t b0, uint32_t b1) {
    asm("mma.sync.aligned.m16n8k8.row.col.f32.tf32.tf32.f32 "
        "{%0,%1,%2,%3}, {%4,%5,%6,%7}, {%8,%9}, {%0,%1,%2,%3};"
        : "+f"(d0), "+f"(d1), "+f"(d2), "+f"(d3)
        : "r"(a0), "r"(a1), "r"(a2), "r"(a3), "r"(b0), "r"(b1));
}

// ---------------- zero init (deg + layer-1 attention accumulators) ----------
__global__ void zero_k() {
    int i = blockIdx.x * blockDim.x + threadIdx.x;
    if (i < NN) g_deg[i] = 0;
    if (i < NN * H1) { g_asrc1[i] = 0.f; g_adst1[i] = 0.f; }
}

// 4 independent edges per thread -> MLP 4 on the gmem atomics
#define EPT 4
__global__ void hist_k(const int* __restrict__ ei) {
    int base = blockIdx.x * (256 * EPT) + threadIdx.x;
#pragma unroll
    for (int k = 0; k < EPT; k++) {
        int i = base + k * 256;
        if (i < NE) atomicAdd(&g_deg[ei[NE + i]], 1);
    }
}

// Coalesced single-block scan: 49 rounds of 1024 contiguous elements.
// Intra-warp shfl scan + warp-sum scan; coalesced loads and stores.
__global__ void scan_k() {
    __shared__ int wsum[32];
    const int t = threadIdx.x;
    const int lane = t & 31, wid = t >> 5;
    const int ROUNDS = (NN + 1023) / 1024;   // 49
    int carry = 0;
    for (int r = 0; r < ROUNDS; r++) {
        int idx = r * 1024 + t;
        int d = (idx < NN) ? g_deg[idx] : 0;
        // inclusive scan within warp
        int v = d;
#pragma unroll
        for (int o = 1; o < 32; o <<= 1) {
            int u = __shfl_up_sync(0xffffffffu, v, o);
            if (lane >= o) v += u;
        }
        if (lane == 31) wsum[wid] = v;
        __syncthreads();
        if (wid == 0) {
            int w = wsum[lane];
#pragma unroll
            for (int o = 1; o < 32; o <<= 1) {
                int u = __shfl_up_sync(0xffffffffu, w, o);
                if (lane >= o) w += u;
            }
            wsum[lane] = w;               // inclusive prefix of warp sums
        }
        __syncthreads();
        int warp_off = (wid > 0) ? wsum[wid - 1] : 0;
        int excl = carry + warp_off + v - d;
        if (idx < NN) { g_off[idx] = excl; g_cur[idx] = excl; }
        carry += wsum[31];                // block total this round
        __syncthreads();                  // protect wsum before next round
    }
    if (t == 0) g_off[NN] = carry;
}

__global__ void fill_k(const int* __restrict__ ei) {
    int base = blockIdx.x * (256 * EPT) + threadIdx.x;
#pragma unroll
    for (int k = 0; k < EPT; k++) {
        int i = base + k * 256;
        if (i < NE) {
            int d = ei[NE + i];
            int p = atomicAdd(&g_cur[d], 1);
            g_csr_src[p] = ei[i];
        }
    }
}

// ---------------- GEMM1 (tf32 tensor cores + fused att1 coefficients) -------
// g_hW1h = fp16(x @ W1). 128x128 block tile, BK=16, register-prefetch staging
// (fp32 -> tf32 at SMEM store), mma.sync.m16n8k8 tf32 math.
// Epilogue stores hW1 (fp16) and atomically accumulates <h,att_src>/<h,att_dst>
// partials (computed from the fp32 accumulators) into g_asrc1/g_adst1.
#define AS_LD 20    // A smem row stride (conflict-free for frag loads)
#define BS_LD 136   // B smem row stride
__global__ __launch_bounds__(256, 2) void gemm1_k(const float* __restrict__ A,
                                                  const float* __restrict__ B,
                                                  const float* __restrict__ att_src,
                                                  const float* __restrict__ att_dst) {
    __shared__ __align__(16) uint32_t As[128 * AS_LD];  // [row][k] tf32
    __shared__ __align__(16) uint32_t Bs[16 * BS_LD];   // [k][n]  tf32
    const int by = blockIdx.y, bx = blockIdx.x;
    const int tid = threadIdx.x;
    const int lane = tid & 31, w = tid >> 5;
    const int wr = w & 3, wc = w >> 2;
    const int g = lane >> 2, c = lane & 3;

    float d[2][8][4];                          // [m-tile][n-tile][frag]
#pragma unroll
    for (int mi = 0; mi < 2; mi++)
#pragma unroll
        for (int ni = 0; ni < 8; ni++)
#pragma unroll
            for (int q = 0; q < 4; q++) d[mi][ni][q] = 0.f;

    // staging coordinates (2 slots of 256 float4 each)
    int arr[2], ack[2], brr[2], bcc[2], agr[2];
#pragma unroll
    for (int l = 0; l < 2; l++) {
        int idx = tid + l * 256;
        arr[l] = idx >> 2;                 // A row 0..127
        ack[l] = (idx & 3) << 2;           // A k offset 0,4,8,12
        brr[l] = idx >> 5;                 // B k 0..15
        bcc[l] = (idx & 31) << 2;          // B col 0..124
        agr[l] = by * 128 + arr[l];
    }

    float4 pa[2], pb[2];
#pragma unroll
    for (int l = 0; l < 2; l++) {
        pa[l] = (agr[l] < NN) ? *(const float4*)(A + (size_t)agr[l] * 256 + ack[l])
                              : make_float4(0.f, 0.f, 0.f, 0.f);
        pb[l] = *(const float4*)(B + (size_t)brr[l] * 256 + bx * 128 + bcc[l]);
    }

    for (int k0 = 0; k0 < 256; k0 += 16) {
        // convert to tf32 and store staged tiles
#pragma unroll
        for (int l = 0; l < 2; l++) {
            uint4 av; av.x = f2tf(pa[l].x); av.y = f2tf(pa[l].y);
                     av.z = f2tf(pa[l].z); av.w = f2tf(pa[l].w);
            *(uint4*)&As[arr[l] * AS_LD + ack[l]] = av;
            uint4 bv; bv.x = f2tf(pb[l].x); bv.y = f2tf(pb[l].y);
                     bv.z = f2tf(pb[l].z); bv.w = f2tf(pb[l].w);
            *(uint4*)&Bs[brr[l] * BS_LD + bcc[l]] = bv;
        }
        __syncthreads();

        if (k0 < 240) {
            int kn = k0 + 16;
#pragma unroll
            for (int l = 0; l < 2; l++) {
                pa[l] = (agr[l] < NN) ? *(const float4*)(A + (size_t)agr[l] * 256 + kn + ack[l])
                                      : make_float4(0.f, 0.f, 0.f, 0.f);
                pb[l] = *(const float4*)(B + (size_t)(kn + brr[l]) * 256 + bx * 128 + bcc[l]);
            }
        }

#pragma unroll
        for (int ks = 0; ks < 2; ks++) {
            const int kb = ks * 8;
            uint32_t a[2][4];
#pragma unroll
            for (int mi = 0; mi < 2; mi++) {
                int rowb = wr * 32 + mi * 16 + g;
                a[mi][0] = As[(rowb)     * AS_LD + kb + c];
                a[mi][1] = As[(rowb + 8) * AS_LD + kb + c];
                a[mi][2] = As[(rowb)     * AS_LD + kb + c + 4];
                a[mi][3] = As[(rowb + 8) * AS_LD + kb + c + 4];
            }
            uint32_t bf[8][2];
#pragma unroll
            for (int ni = 0; ni < 8; ni++) {
                int colb = wc * 64 + ni * 8 + g;
                bf[ni][0] = Bs[(kb + c)     * BS_LD + colb];
                bf[ni][1] = Bs[(kb + c + 4) * BS_LD + colb];
            }
#pragma unroll
            for (int mi = 0; mi < 2; mi++)
#pragma unroll
                for (int ni = 0; ni < 8; ni++)
                    mma_tf32(d[mi][ni][0], d[mi][ni][1], d[mi][ni][2], d[mi][ni][3],
                             a[mi][0], a[mi][1], a[mi][2], a[mi][3],
                             bf[ni][0], bf[ni][1]);
        }
        __syncthreads();
    }

    // ---- epilogue: store hW1 (fp16) + fused attention partials (fp32) ----
    const int head = bx * 2 + wc;              // this warp's 64-col chunk = one head
    float asv[16], adv[16];
#pragma unroll
    for (int ni = 0; ni < 8; ni++) {
        float2 s = *(const float2*)(att_src + head * 64 + ni * 8 + 2 * c);
        float2 t = *(const float2*)(att_dst + head * 64 + ni * 8 + 2 * c);
        asv[2 * ni] = s.x; asv[2 * ni + 1] = s.y;
        adv[2 * ni] = t.x; adv[2 * ni + 1] = t.y;
    }
    const int colbase = bx * 128 + wc * 64;
#pragma unroll
    for (int mi = 0; mi < 2; mi++) {
#pragma unroll
        for (int half = 0; half < 2; half++) {
            int R = by * 128 + wr * 32 + mi * 16 + half * 8 + g;
            if (R < NN) {
                float ss = 0.f, dd = 0.f;
#pragma unroll
                for (int ni = 0; ni < 8; ni++) {
                    float v0 = d[mi][ni][half * 2 + 0];
                    float v1 = d[mi][ni][half * 2 + 1];
                    *(__half2*)(g_hW1h + (size_t)R * 256 + colbase + ni * 8 + 2 * c) =
                        __floats2half2_rn(v0, v1);
                    ss += v0 * asv[2 * ni] + v1 * asv[2 * ni + 1];
                    dd += v0 * adv[2 * ni] + v1 * adv[2 * ni + 1];
                }
                atomicAdd(&g_asrc1[R * 4 + head], ss);
                atomicAdd(&g_adst1[R * 4 + head], dd);
            }
        }
    }
}

// ---------------- layer-1 online softmax + aggregate + bias + ELU -----------
// One warp per destination node. Lane owns channels lane*8..lane*8+7
// (head = lane>>3). Online softmax; depth-2 software pipeline; fp16 h gather.
__global__ __launch_bounds__(256) void agg1_k(const float* __restrict__ b1,
                                              float* __restrict__ hout) {
    int node = (blockIdx.x * blockDim.x + threadIdx.x) >> 5;
    int lane = threadIdx.x & 31;
    if (node >= NN) return;

    int start = g_off[node], end = g_off[node + 1];
    int cnt = end - start;

    int head = lane >> 3;
    float adst = g_adst1[node * 4 + head];

    float m = -CUDART_INF_F;
    float denom = 0.f;
    float acc[8];
#pragma unroll
    for (int q = 0; q < 8; q++) acc[q] = 0.f;

    if (cnt > 0) {
        float asP[2];
        uint4 hP[2];                      // 8 halfs = this lane's channels
        {
            int j0 = g_csr_src[start];
            asP[0] = g_asrc1[j0 * 4 + head];
            hP[0] = *(const uint4*)(g_hW1h + (size_t)j0 * 256 + lane * 8);
        }
        if (cnt > 1) {
            int j1 = g_csr_src[start + 1];
            asP[1] = g_asrc1[j1 * 4 + head];
            hP[1] = *(const uint4*)(g_hW1h + (size_t)j1 * 256 + lane * 8);
        }
        for (int i = 0; i < cnt; i++) {
            int slot = i & 1;
            float as_c = asP[slot]; uint4 h_c = hP[slot];
            if (i + 2 < cnt) {
                int jn = g_csr_src[start + i + 2];
                asP[slot] = g_asrc1[jn * 4 + head];
                hP[slot] = *(const uint4*)(g_hW1h + (size_t)jn * 256 + lane * 8);
            }
            float v = leaky(as_c + adst);
            if (v > m) {                 // online rescale (expf(-inf)=0 seeds cleanly)
                float sc = __expf(m - v);
                denom *= sc;
#pragma unroll
                for (int q = 0; q < 8; q++) acc[q] *= sc;
                m = v;
            }
            float ex = __expf(v - m);
            denom += ex;
            float2 f0 = __half22float2(*(const __half2*)&h_c.x);
            float2 f1 = __half22float2(*(const __half2*)&h_c.y);
            float2 f2 = __half22float2(*(const __half2*)&h_c.z);
            float2 f3 = __half22float2(*(const __half2*)&h_c.w);
            acc[0] += ex * f0.x; acc[1] += ex * f0.y;
            acc[2] += ex * f1.x; acc[3] += ex * f1.y;
            acc[4] += ex * f2.x; acc[5] += ex * f2.y;
            acc[6] += ex * f3.x; acc[7] += ex * f3.y;
        }
    }
    float inv = 1.f / (denom + 1e-16f);
    int c0 = lane * 8;
    const float4* bp = (const float4*)(b1 + c0);
    float4 bb0 = bp[0], bb1 = bp[1];
    float4 o0, o1;
    o0.x = elu(acc[0] * inv + bb0.x); o0.y = elu(acc[1] * inv + bb0.y);
    o0.z = elu(acc[2] * inv + bb0.z); o0.w = elu(acc[3] * inv + bb0.w);
    o1.x = elu(acc[4] * inv + bb1.x); o1.y = elu(acc[5] * inv + bb1.y);
    o1.z = elu(acc[6] * inv + bb1.z); o1.w = elu(acc[7] * inv + bb1.w);
    float4* op = (float4*)(hout + (size_t)node * 256 + c0);
    op[0] = o0; op[1] = o1;
}

// ---------------- GEMM2 + layer-2 attention coefficients --------------------
// g_hW2 = elu_h[NN,256] @ W2[256,32]; fused a_src2/a_dst2 via warp reduction.
__global__ __launch_bounds__(256) void gemm2_k(const float* __restrict__ h,
                                               const float* __restrict__ W2,
                                               const float* __restrict__ att_src2,
                                               const float* __restrict__ att_dst2) {
    __shared__ float sW[256 * 32];
    int tid = threadIdx.x;
    for (int i = tid; i < 256 * 32; i += 256) sW[i] = W2[i];
    __syncthreads();
    int lane = tid & 31, wid = tid >> 5;
    int n = blockIdx.x * 8 + wid;
    if (n >= NN) return;

    const float4* hp = (const float4*)(h + (size_t)n * 256);
    float acc = 0.f;
#pragma unroll
    for (int k4 = 0; k4 < 64; k4++) {
        float4 hv = hp[k4];
        acc += hv.x * sW[(k4 * 4 + 0) * 32 + lane];
        acc += hv.y * sW[(k4 * 4 + 1) * 32 + lane];
        acc += hv.z * sW[(k4 * 4 + 2) * 32 + lane];
        acc += hv.w * sW[(k4 * 4 + 3) * 32 + lane];
    }
    g_hW2[n * 32 + lane] = acc;
    float s = acc * att_src2[lane];
    float d = acc * att_dst2[lane];
#pragma unroll
    for (int o = 16; o; o >>= 1) {
        s += __shfl_xor_sync(0xffffffffu, s, o);
        d += __shfl_xor_sync(0xffffffffu, d, o);
    }
    if (lane == 0) { g_asrc2[n] = s; g_adst2[n] = d; }
}

// ---------------- layer-2 online softmax + aggregate + bias -----------------
// Depth-2 software pipeline like agg1.
__global__ __launch_bounds__(256) void agg2_k(const float* __restrict__ b2,
                                              float* __restrict__ out2) {
    int node = (blockIdx.x * blockDim.x + threadIdx.x) >> 5;
    int lane = threadIdx.x & 31;
    if (node >= NN) return;

    int start = g_off[node], end = g_off[node + 1];
    int cnt = end - start;
    float adst = g_adst2[node];

    float m = -CUDART_INF_F;
    float denom = 0.f, acc = 0.f;
    if (cnt > 0) {
        float asP[2], hvP[2];
        {
            int j0 = g_csr_src[start];
            asP[0] = g_asrc2[j0];
            hvP[0] = g_hW2[j0 * 32 + lane];
        }
        if (cnt > 1) {
            int j1 = g_csr_src[start + 1];
            asP[1] = g_asrc2[j1];
            hvP[1] = g_hW2[j1 * 32 + lane];
        }
        for (int i = 0; i < cnt; i++) {
            int slot = i & 1;
            float as_c = asP[slot], hv_c = hvP[slot];
            if (i + 2 < cnt) {
                int jn = g_csr_src[start + i + 2];
                asP[slot] = g_asrc2[jn];
                hvP[slot] = g_hW2[jn * 32 + lane];
            }
            float v = leaky(as_c + adst);
            if (v > m) {                 // online rescale
                float sc = __expf(m - v);
                denom *= sc;
                acc *= sc;
                m = v;
            }
            float ex = __expf(v - m);
            denom += ex;
            acc += ex * hv_c;
        }
    }
    out2[(size_t)node * 32 + lane] = acc / (denom + 1e-16f) + b2[lane];
}

// ---------------- launch ----------------------------------------------------
extern "C" void kernel_launch(void* const* d_in, const int* in_sizes, int n_in,
                              void* d_out, int out_size) {
    const float* x   = (const float*)d_in[0];
    const float* W1  = (const float*)d_in[1];
    const float* as1 = (const float*)d_in[2];
    const float* ad1 = (const float*)d_in[3];
    const float* b1  = (const float*)d_in[4];
    const float* W2  = (const float*)d_in[5];
    const float* as2 = (const float*)d_in[6];
    const float* ad2 = (const float*)d_in[7];
    const float* b2  = (const float*)d_in[8];
    const int*   ei  = (const int*)d_in[9];

    float* out2 = (float*)d_out;                  // [NN, 32]
    float* hout = (float*)d_out + (size_t)NN * 32; // [NN, 256] (= elu layer-1 out)

    const int warpBlocks = (NN * 32 + 255) / 256;      // warp-per-node kernels
    const int edgeBlocks4 = (NE + 256 * EPT - 1) / (256 * EPT);
    const int zeroBlocks = (NN * H1 + 255) / 256;

    // zero (deg + att1 accumulators), then CSR build (independent of GEMM1)
    zero_k<<<zeroBlocks, 256>>>();
    hist_k<<<edgeBlocks4, 256>>>(ei);
    scan_k<<<1, 1024>>>();
    fill_k<<<edgeBlocks4, 256>>>(ei);

    // Layer 1 (tf32 tensor-core gemm1 fuses the att1 coefficient computation)
    gemm1_k<<<dim3(2, (NN + 127) / 128), 256>>>(x, W1, as1, ad1);
    agg1_k<<<warpBlocks, 256>>>(b1, hout);

    // Layer 2
    gemm2_k<<<(NN + 7) / 8, 256>>>(hout, W2, as2, ad2);
    agg2_k<<<warpBlocks, 256>>>(b2, out2);
}